// round 7
// baseline (speedup 1.0000x reference)
#include <cuda_runtime.h>
#include <cuda_fp16.h>
#include <cstdint>
#include <cstddef>

#define IN_F   4096
#define OUT_F  4096
#define MTOT   8192   // 4 * 2048

// ---------------- scratch (static device globals: allocation-free) -----------
__device__ __half g_Xh[(size_t)MTOT * IN_F];   // x in fp16           (64 MiB)
__device__ __half g_Wh[(size_t)OUT_F * IN_F];  // W_eff in fp16       (32 MiB)

// ---------------- PTX helpers ----------------
__device__ __forceinline__ uint32_t smem_u32(const void* p) {
    uint32_t r;
    asm("{ .reg .u64 t; cvta.to.shared.u64 t, %1; cvt.u32.u64 %0, t; }"
        : "=r"(r) : "l"(p));
    return r;
}
__device__ __forceinline__ void cp_async16(uint32_t dst, const void* src) {
    asm volatile("cp.async.cg.shared.global [%0], [%1], 16;" :: "r"(dst), "l"(src));
}
#define CP_COMMIT() asm volatile("cp.async.commit_group;" ::: "memory")
#define CP_WAIT(n)  asm volatile("cp.async.wait_group %0;" :: "n"(n) : "memory")

__device__ __forceinline__ void ldsm_x4(uint32_t* r, uint32_t addr) {
    asm volatile("ldmatrix.sync.aligned.m8n8.x4.shared.b16 {%0,%1,%2,%3}, [%4];"
                 : "=r"(r[0]), "=r"(r[1]), "=r"(r[2]), "=r"(r[3]) : "r"(addr));
}
__device__ __forceinline__ void mma16816(float* c, const uint32_t* a, const uint32_t* b) {
    asm volatile(
        "mma.sync.aligned.m16n8k16.row.col.f32.f16.f16.f32 "
        "{%0,%1,%2,%3}, {%4,%5,%6,%7}, {%8,%9}, {%0,%1,%2,%3};"
        : "+f"(c[0]), "+f"(c[1]), "+f"(c[2]), "+f"(c[3])
        : "r"(a[0]), "r"(a[1]), "r"(a[2]), "r"(a[3]), "r"(b[0]), "r"(b[1]));
}

// ---------------- kernel 1: x fp32 -> fp16 ----------------
__global__ void k_convert_x(const float4* __restrict__ x) {
    const int n4 = MTOT * IN_F / 4;
    uint2* __restrict__ out = reinterpret_cast<uint2*>(g_Xh);
    int stride = gridDim.x * blockDim.x;
    for (int i = blockIdx.x * blockDim.x + threadIdx.x; i < n4; i += stride) {
        float4 v = x[i];
        __half2 lo = __floats2half2_rn(v.x, v.y);
        __half2 hi = __floats2half2_rn(v.z, v.w);
        uint2 o;
        o.x = *reinterpret_cast<uint32_t*>(&lo);
        o.y = *reinterpret_cast<uint32_t*>(&hi);
        out[i] = o;
    }
}

// ---------------- kernel 2: W_eff = dequant + LoRA fold -> fp16 --------------
#define TO 32
#define TI 512
__global__ void k_fold_w(const int* __restrict__ qw, const float* __restrict__ qs,
                         const float* __restrict__ A, const float* __restrict__ B) {
    __shared__ float As[16][TI + 4];
    __shared__ float Bs[TO][16];
    __shared__ float Ss[TO];
    const int tid = threadIdx.x;                  // 256
    const int o0 = blockIdx.x * TO;
    for (int t = tid; t < TO * 16; t += 256)
        Bs[t / 16][t % 16] = B[(size_t)(o0 + t / 16) * 16 + (t % 16)];
    if (tid < TO) Ss[tid] = qs[o0 + tid];
    const int ro = tid >> 3;    // row 0..31
    const int l8 = tid & 7;     // 0..7
    for (int cb = 0; cb < IN_F; cb += TI) {
        __syncthreads();
        for (int t = tid; t < 16 * (TI / 4); t += 256) {
            int r = t / (TI / 4), j = t % (TI / 4);
            float4 v = reinterpret_cast<const float4*>(A + (size_t)r * IN_F + cb)[j];
            *reinterpret_cast<float4*>(&As[r][j * 4]) = v;
        }
        __syncthreads();
        const float s = Ss[ro];
        const float* brow = Bs[ro];
        #pragma unroll 4
        for (int j = 0; j < TI / 32; ++j) {
            int il = l8 * 4 + j * 32;
            int4 q4 = *reinterpret_cast<const int4*>(&qw[(size_t)(o0 + ro) * IN_F + cb + il]);
            float a0 = q4.x * s, a1 = q4.y * s, a2 = q4.z * s, a3 = q4.w * s;
            #pragma unroll
            for (int r = 0; r < 16; ++r) {
                float b2 = 2.0f * brow[r];
                a0 = fmaf(b2, As[r][il + 0], a0);
                a1 = fmaf(b2, As[r][il + 1], a1);
                a2 = fmaf(b2, As[r][il + 2], a2);
                a3 = fmaf(b2, As[r][il + 3], a3);
            }
            __half2 h0 = __floats2half2_rn(a0, a1);
            __half2 h1 = __floats2half2_rn(a2, a3);
            uint2 o;
            o.x = *reinterpret_cast<uint32_t*>(&h0);
            o.y = *reinterpret_cast<uint32_t*>(&h1);
            *reinterpret_cast<uint2*>(&g_Wh[(size_t)(o0 + ro) * IN_F + cb + il]) = o;
        }
    }
}

// ---------------- kernel 3: pipelined mma.sync fp16 GEMM, 2 CTAs/SM ---------
// BM=128, BN=128, BK=64, 3 stages (96 KB/CTA -> 2 co-resident CTAs).
// 8 warps as 2(m) x 4(n); warp tile 64x32; A-fragment ping-pong across ks.
#define BM 128
#define BN 128
#define BK 64
#define NSTAGES 3
#define A_BYTES (BM * 128)                  // 16384
#define B_BYTES (BN * 128)                  // 16384
#define STAGE_BYTES (A_BYTES + B_BYTES)     // 32768
#define GEMM_SMEM (NSTAGES * STAGE_BYTES)   // 98304 per CTA
#define GEMM_THREADS 256
#define KCH (IN_F / BK)                     // 64

__device__ __forceinline__ void load_stage(uint32_t sb, int slot, int c,
                                           const __half* ga_base, const __half* gb_base,
                                           int tid) {
    uint32_t abase = sb + slot * STAGE_BYTES;
    uint32_t bbase = abase + A_BYTES;
    const __half* ga = ga_base + c * BK;
    const __half* gb = gb_base + c * BK;
    #pragma unroll
    for (int it = 0; it < (BM + BN) * 8 / GEMM_THREADS; ++it) {   // 8
        int t = tid + it * GEMM_THREADS;
        int chunk = t & 7;
        int row = (t >> 3);
        if (t < BM * 8) {
            uint32_t off = (uint32_t)(row * 128 + ((chunk ^ (row & 7)) << 4));
            cp_async16(abase + off, ga + (size_t)row * IN_F + chunk * 8);
        } else {
            row -= BM;
            uint32_t off = (uint32_t)(row * 128 + ((chunk ^ (row & 7)) << 4));
            cp_async16(bbase + off, gb + (size_t)row * IN_F + chunk * 8);
        }
    }
}

__device__ __forceinline__ void lda_frags(uint32_t* af, uint32_t stage_base,
                                          int ks, int wm, int lid) {
    #pragma unroll
    for (int i = 0; i < 4; ++i) {
        int row = wm * 64 + i * 16 + (lid & 15);
        int chunk = ks * 2 + (lid >> 4);
        uint32_t addr = stage_base + (uint32_t)(row * 128) + (((chunk ^ (row & 7)) & 7) << 4);
        ldsm_x4(af + i * 4, addr);
    }
}

__global__ void __launch_bounds__(GEMM_THREADS, 2)
k_gemm(const float* __restrict__ bias, float* __restrict__ out) {
    extern __shared__ char smem[];
    uint32_t sb = smem_u32(smem);
    const int tid = threadIdx.x;
    const int wid = tid >> 5, lid = tid & 31;
    const int wm = wid & 1;          // 0..1  (m: 64-row halves)
    const int wn = wid >> 1;         // 0..3  (n: 32-col slices)
    const int m0 = blockIdx.y * BM;
    const int n0 = blockIdx.x * BN;
    const __half* ga_base = g_Xh + (size_t)m0 * IN_F;
    const __half* gb_base = g_Wh + (size_t)n0 * IN_F;

    float ac[4][4][4];
    #pragma unroll
    for (int i = 0; i < 4; ++i)
        #pragma unroll
        for (int j = 0; j < 4; ++j)
            #pragma unroll
            for (int k = 0; k < 4; ++k) ac[i][j][k] = 0.0f;

    // prologue: stages 0,1 <- chunks 0,1
    load_stage(sb, 0, 0, ga_base, gb_base, tid); CP_COMMIT();
    load_stage(sb, 1, 1, ga_base, gb_base, tid); CP_COMMIT();

    int slot = 0;
    for (int c = 0; c < KCH; ++c) {
        CP_WAIT(1);
        __syncthreads();
        if (c + 2 < KCH) {
            int nslot = slot + 2; if (nslot >= NSTAGES) nslot -= NSTAGES;
            load_stage(sb, nslot, c + 2, ga_base, gb_base, tid);
            CP_COMMIT();
        }

        uint32_t stage_base = sb + slot * STAGE_BYTES;
        uint32_t Bb = stage_base + A_BYTES;
        uint32_t af[2][16];
        lda_frags(af[0], stage_base, 0, wm, lid);

        #pragma unroll
        for (int ks = 0; ks < BK / 16; ++ks) {           // 4
            int cur = ks & 1;
            uint32_t bf[8];
            #pragma unroll
            for (int j = 0; j < 2; ++j) {
                int row = wn * 32 + j * 16 + ((lid >> 4) << 3) + (lid & 7);
                int chunk = ks * 2 + ((lid >> 3) & 1);
                uint32_t addr = Bb + (uint32_t)(row * 128) + (((chunk ^ (row & 7)) & 7) << 4);
                ldsm_x4(bf + j * 4, addr);
            }
            if (ks + 1 < BK / 16)
                lda_frags(af[cur ^ 1], stage_base, ks + 1, wm, lid);
            #pragma unroll
            for (int i = 0; i < 4; ++i) {
                #pragma unroll
                for (int jj = 0; jj < 4; ++jj) {
                    mma16816(ac[i][jj], &af[cur][i * 4], &bf[(jj >> 1) * 4 + (jj & 1) * 2]);
                }
            }
        }
        ++slot; if (slot >= NSTAGES) slot -= NSTAGES;
    }

    // epilogue: write 64x32 warp tile with bias
    const int mbase = m0 + wm * 64 + (lid >> 2);
    const int nbase = n0 + wn * 32 + (lid & 3) * 2;
    #pragma unroll
    for (int jj = 0; jj < 4; ++jj) {
        int n = nbase + jj * 8;
        float b0 = bias[n], b1 = bias[n + 1];
        #pragma unroll
        for (int i = 0; i < 4; ++i) {
            int m = mbase + i * 16;
            float2 v0 = make_float2(ac[i][jj][0] + b0, ac[i][jj][1] + b1);
            float2 v1 = make_float2(ac[i][jj][2] + b0, ac[i][jj][3] + b1);
            *reinterpret_cast<float2*>(&out[(size_t)m * OUT_F + n]) = v0;
            *reinterpret_cast<float2*>(&out[(size_t)(m + 8) * OUT_F + n]) = v1;
        }
    }
}

// ---------------- launcher ----------------
extern "C" void kernel_launch(void* const* d_in, const int* in_sizes, int n_in,
                              void* d_out, int out_size) {
    const float* x    = (const float*)d_in[0];
    const int*   qw   = (const int*)  d_in[1];
    const float* qs   = (const float*)d_in[2];
    const float* bias = (const float*)d_in[3];
    const float* lA   = (const float*)d_in[4];
    const float* lB   = (const float*)d_in[5];
    float* out = (float*)d_out;

    cudaFuncSetAttribute(k_gemm, cudaFuncAttributeMaxDynamicSharedMemorySize, GEMM_SMEM);

    k_convert_x<<<4096, 256>>>(reinterpret_cast<const float4*>(x));
    k_fold_w<<<OUT_F / TO, 256>>>(qw, qs, lA, lB);
    k_gemm<<<dim3(OUT_F / BN, MTOT / BM), GEMM_THREADS, GEMM_SMEM>>>(bias, out);
}

// round 8
// speedup vs baseline: 1.5647x; 1.5647x over previous
#include <cuda_runtime.h>
#include <cuda_fp16.h>
#include <cstdint>
#include <cstddef>

#define IN_F   4096
#define OUT_F  4096
#define MTOT   8192   // 4 * 2048

// ---------------- scratch (static device globals: allocation-free) -----------
// Tile-major, pre-swizzled layouts (exactly what the GEMM wants in smem):
// g_Xh: [mtile(64)][kchunk(64)] blocks of 16384B = 128 rows x 128B (swizzled)
// g_Wh: [ntile(16)][kchunk(64)] blocks of 32768B = 256 rows x 128B (swizzled)
__device__ __half g_Xh[(size_t)MTOT * IN_F];   // 64 MiB
__device__ __half g_Wh[(size_t)OUT_F * IN_F];  // 32 MiB

// ---------------- PTX helpers ----------------
__device__ __forceinline__ uint32_t smem_u32(const void* p) {
    uint32_t r;
    asm("{ .reg .u64 t; cvta.to.shared.u64 t, %1; cvt.u32.u64 %0, t; }"
        : "=r"(r) : "l"(p));
    return r;
}
__device__ __forceinline__ void ldsm_x4(uint32_t* r, uint32_t addr) {
    asm volatile("ldmatrix.sync.aligned.m8n8.x4.shared.b16 {%0,%1,%2,%3}, [%4];"
                 : "=r"(r[0]), "=r"(r[1]), "=r"(r[2]), "=r"(r[3]) : "r"(addr));
}
__device__ __forceinline__ void mma16816(float* c, const uint32_t* a, const uint32_t* b) {
    asm volatile(
        "mma.sync.aligned.m16n8k16.row.col.f32.f16.f16.f32 "
        "{%0,%1,%2,%3}, {%4,%5,%6,%7}, {%8,%9}, {%0,%1,%2,%3};"
        : "+f"(c[0]), "+f"(c[1]), "+f"(c[2]), "+f"(c[3])
        : "r"(a[0]), "r"(a[1]), "r"(a[2]), "r"(a[3]), "r"(b[0]), "r"(b[1]));
}
__device__ __forceinline__ void bulk_g2s(uint32_t dst, const void* src, uint32_t bytes,
                                         uint32_t mbar) {
    asm volatile(
        "cp.async.bulk.shared::cta.global.mbarrier::complete_tx::bytes [%0], [%1], %2, [%3];"
        :: "r"(dst), "l"(src), "r"(bytes), "r"(mbar) : "memory");
}
#define MBARRIER_INIT(addr, cnt) \
    asm volatile("mbarrier.init.shared.b64 [%0], %1;" :: "r"((uint32_t)(addr)), "r"((uint32_t)(cnt)) : "memory")
#define MBARRIER_EXPECT_TX(addr, bytes) \
    asm volatile("mbarrier.arrive.expect_tx.shared.b64 _, [%0], %1;" :: "r"((uint32_t)(addr)), "r"((uint32_t)(bytes)) : "memory")
#define MBARRIER_WAIT_PARITY(mbar_smem_addr, phase_parity) do {                         \
    uint32_t _mbar = (uint32_t)(mbar_smem_addr);                                        \
    uint32_t _parity = (uint32_t)(phase_parity);                                        \
    uint32_t _done;                                                                     \
    asm volatile("{\n\t.reg .pred p;\n\t"                                               \
        "mbarrier.try_wait.parity.acquire.cta.shared::cta.b64 p, [%1], %2;\n\t"         \
        "selp.b32 %0, 1, 0, p;\n\t}"                                                    \
        : "=r"(_done) : "r"(_mbar), "r"(_parity) : "memory");                           \
    if (!_done) {                                                                       \
        asm volatile("{\n\t.reg .pred P1;\n\t"                                          \
            "WAIT_LOOP_%=:\n\t"                                                         \
            "mbarrier.try_wait.parity.acquire.cta.shared::cta.b64 P1, [%0], %1, 0x989680;\n\t" \
            "@P1 bra.uni WAIT_DONE_%=;\n\t"                                             \
            "bra.uni WAIT_LOOP_%=;\n\t"                                                 \
            "WAIT_DONE_%=:\n\t}"                                                        \
            :: "r"(_mbar), "r"(_parity) : "memory");                                    \
    }                                                                                   \
} while (0)

// ---------------- kernel 1: x fp32 -> fp16, tile-major swizzled --------------
__global__ void k_convert_x(const float4* __restrict__ x) {
    const int ngroups = MTOT * IN_F / 8;          // 8 halfs (16B) per group
    int stride = gridDim.x * blockDim.x;
    for (int g = blockIdx.x * blockDim.x + threadIdx.x; g < ngroups; g += stride) {
        float4 v0 = x[g * 2], v1 = x[g * 2 + 1];
        __half2 h0 = __floats2half2_rn(v0.x, v0.y);
        __half2 h1 = __floats2half2_rn(v0.z, v0.w);
        __half2 h2 = __floats2half2_rn(v1.x, v1.y);
        __half2 h3 = __floats2half2_rn(v1.z, v1.w);
        uint4 o;
        o.x = *reinterpret_cast<uint32_t*>(&h0);
        o.y = *reinterpret_cast<uint32_t*>(&h1);
        o.z = *reinterpret_cast<uint32_t*>(&h2);
        o.w = *reinterpret_cast<uint32_t*>(&h3);
        int m = g >> 9;                 // 512 groups per row
        int kg = g & 511;
        int kchunk = kg >> 3, chunk = kg & 7;
        int r = m & 127, mtile = m >> 7;
        size_t off = ((size_t)(mtile * 64 + kchunk) << 14)
                   + (uint32_t)(r * 128 + (((chunk ^ (r & 7)) & 7) << 4));
        *reinterpret_cast<uint4*>(reinterpret_cast<char*>(g_Xh) + off) = o;
    }
}

// ---------------- kernel 2: W_eff fold -> fp16, tile-major swizzled ----------
#define TO 32
#define TI 512
__global__ void k_fold_w(const int* __restrict__ qw, const float* __restrict__ qs,
                         const float* __restrict__ A, const float* __restrict__ B) {
    __shared__ float As[16][TI + 4];
    __shared__ float Bs[TO][16];
    __shared__ float Ss[TO];
    const int tid = threadIdx.x;                  // 256
    const int o0 = blockIdx.x * TO;
    for (int t = tid; t < TO * 16; t += 256)
        Bs[t / 16][t % 16] = B[(size_t)(o0 + t / 16) * 16 + (t % 16)];
    if (tid < TO) Ss[tid] = qs[o0 + tid];
    const int ro = tid >> 3;    // row 0..31
    const int l8 = tid & 7;     // 0..7
    const int o = o0 + ro;
    const int ntile = o >> 8, rr = o & 255;
    for (int cb = 0; cb < IN_F; cb += TI) {
        __syncthreads();
        for (int t = tid; t < 16 * (TI / 4); t += 256) {
            int r = t / (TI / 4), j = t % (TI / 4);
            float4 v = reinterpret_cast<const float4*>(A + (size_t)r * IN_F + cb)[j];
            *reinterpret_cast<float4*>(&As[r][j * 4]) = v;
        }
        __syncthreads();
        const float s = Ss[ro];
        const float* brow = Bs[ro];
        #pragma unroll 4
        for (int j = 0; j < TI / 32; ++j) {
            int il = l8 * 4 + j * 32;
            int4 q4 = *reinterpret_cast<const int4*>(&qw[(size_t)o * IN_F + cb + il]);
            float a0 = q4.x * s, a1 = q4.y * s, a2 = q4.z * s, a3 = q4.w * s;
            #pragma unroll
            for (int r = 0; r < 16; ++r) {
                float b2 = 2.0f * brow[r];
                a0 = fmaf(b2, As[r][il + 0], a0);
                a1 = fmaf(b2, As[r][il + 1], a1);
                a2 = fmaf(b2, As[r][il + 2], a2);
                a3 = fmaf(b2, As[r][il + 3], a3);
            }
            __half2 h0 = __floats2half2_rn(a0, a1);
            __half2 h1 = __floats2half2_rn(a2, a3);
            uint2 w;
            w.x = *reinterpret_cast<uint32_t*>(&h0);
            w.y = *reinterpret_cast<uint32_t*>(&h1);
            int col = cb + il;
            int kchunk = col >> 6;
            int c6 = col & 63;
            int chunk = c6 >> 3, within = c6 & 7;   // within in {0,4}
            size_t off = ((size_t)(ntile * 64 + kchunk) << 15)
                       + (uint32_t)(rr * 128 + (((chunk ^ (rr & 7)) & 7) << 4) + within * 2);
            *reinterpret_cast<uint2*>(reinterpret_cast<char*>(g_Wh) + off) = w;
        }
    }
}

// ---------------- kernel 3: bulk-DMA pipelined mma.sync fp16 GEMM ------------
// BM=128, BN=256, BK=64, 4 stages fed by cp.async.bulk + mbarrier.
// 8 warps as 2(m) x 4(n); warp tile 64x64; fragment ping-pong across ks.
#define BM 128
#define BN 256
#define BK 64
#define NST 4
#define A_SZ (BM * 128)                   // 16384
#define B_SZ (BN * 128)                   // 32768
#define ST_SZ (A_SZ + B_SZ)               // 49152
#define SMEM_T0 1024
#define GEMM_SMEM (SMEM_T0 + NST * ST_SZ) // 197632
#define GEMM_THREADS 256
#define KCH (IN_F / BK)                   // 64

__device__ __forceinline__ void lda_frags(uint32_t* af, uint32_t Ab,
                                          int ks, int wm, int lid) {
    #pragma unroll
    for (int i = 0; i < 4; ++i) {
        int row = wm * 64 + i * 16 + (lid & 15);
        int chunk = ks * 2 + (lid >> 4);
        uint32_t addr = Ab + (uint32_t)(row * 128) + (((chunk ^ (row & 7)) & 7) << 4);
        ldsm_x4(af + i * 4, addr);
    }
}
__device__ __forceinline__ void ldb_frags(uint32_t* bf, uint32_t Bb,
                                          int ks, int wn, int lid) {
    #pragma unroll
    for (int j = 0; j < 4; ++j) {
        int row = wn * 64 + j * 16 + ((lid >> 4) << 3) + (lid & 7);
        int chunk = ks * 2 + ((lid >> 3) & 1);
        uint32_t addr = Bb + (uint32_t)(row * 128) + (((chunk ^ (row & 7)) & 7) << 4);
        ldsm_x4(bf + j * 4, addr);
    }
}

__global__ void __launch_bounds__(GEMM_THREADS, 1)
k_gemm(const float* __restrict__ bias, float* __restrict__ out) {
    extern __shared__ char smem[];
    uint32_t sb = smem_u32(smem);
    const int tid = threadIdx.x;
    const int wid = tid >> 5, lid = tid & 31;
    const int wm = wid & 1;          // 0..1  (m: 64-row halves)
    const int wn = wid >> 1;         // 0..3  (n: 64-col slices)
    const int mtile = blockIdx.y;    // 0..63
    const int ntile = blockIdx.x;    // 0..15
    const char* gA = reinterpret_cast<const char*>(g_Xh) + ((size_t)mtile * 64 << 14);
    const char* gB = reinterpret_cast<const char*>(g_Wh) + ((size_t)ntile * 64 << 15);

    float ac[4][8][4];
    #pragma unroll
    for (int i = 0; i < 4; ++i)
        #pragma unroll
        for (int j = 0; j < 8; ++j)
            #pragma unroll
            for (int k = 0; k < 4; ++k) ac[i][j][k] = 0.0f;

    // mbarriers at sb + 8*s
    if (tid == 0) {
        #pragma unroll
        for (int s = 0; s < NST; ++s) MBARRIER_INIT(sb + 8 * s, 1);
    }
    __syncthreads();

    if (tid == 0) {
        #pragma unroll
        for (int c = 0; c < NST; ++c) {
            uint32_t stg = sb + SMEM_T0 + c * ST_SZ;
            MBARRIER_EXPECT_TX(sb + 8 * c, ST_SZ);
            bulk_g2s(stg, gA + ((size_t)c << 14), A_SZ, sb + 8 * c);
            bulk_g2s(stg + A_SZ, gB + ((size_t)c << 15), B_SZ, sb + 8 * c);
        }
    }

    for (int c = 0; c < KCH; ++c) {
        int s = c & (NST - 1);
        MBARRIER_WAIT_PARITY(sb + 8 * s, (uint32_t)((c >> 2) & 1));

        uint32_t Ab = sb + SMEM_T0 + s * ST_SZ;
        uint32_t Bb = Ab + A_SZ;
        uint32_t af[2][16], bf[2][16];
        lda_frags(af[0], Ab, 0, wm, lid);
        ldb_frags(bf[0], Bb, 0, wn, lid);
        #pragma unroll
        for (int ks = 0; ks < BK / 16; ++ks) {       // 4
            int cur = ks & 1;
            if (ks + 1 < BK / 16) {
                lda_frags(af[cur ^ 1], Ab, ks + 1, wm, lid);
                ldb_frags(bf[cur ^ 1], Bb, ks + 1, wn, lid);
            }
            #pragma unroll
            for (int i = 0; i < 4; ++i) {
                #pragma unroll
                for (int jj = 0; jj < 8; ++jj) {
                    mma16816(ac[i][jj], &af[cur][i * 4], &bf[cur][(jj >> 1) * 4 + (jj & 1) * 2]);
                }
            }
        }

        __syncthreads();   // all warps done reading stage s
        if (tid == 0 && c + NST < KCH) {
            int nc = c + NST;
            uint32_t stg = sb + SMEM_T0 + s * ST_SZ;
            MBARRIER_EXPECT_TX(sb + 8 * s, ST_SZ);
            bulk_g2s(stg, gA + ((size_t)nc << 14), A_SZ, sb + 8 * s);
            bulk_g2s(stg + A_SZ, gB + ((size_t)nc << 15), B_SZ, sb + 8 * s);
        }
    }

    // epilogue: write 64x64 warp tile with bias
    const int m0 = mtile * BM, n0 = ntile * BN;
    const int mbase = m0 + wm * 64 + (lid >> 2);
    const int nbase = n0 + wn * 64 + (lid & 3) * 2;
    #pragma unroll
    for (int jj = 0; jj < 8; ++jj) {
        int n = nbase + jj * 8;
        float b0 = bias[n], b1 = bias[n + 1];
        #pragma unroll
        for (int i = 0; i < 4; ++i) {
            int m = mbase + i * 16;
            float2 v0 = make_float2(ac[i][jj][0] + b0, ac[i][jj][1] + b1);
            float2 v1 = make_float2(ac[i][jj][2] + b0, ac[i][jj][3] + b1);
            *reinterpret_cast<float2*>(&out[(size_t)m * OUT_F + n]) = v0;
            *reinterpret_cast<float2*>(&out[(size_t)(m + 8) * OUT_F + n]) = v1;
        }
    }
}

// ---------------- launcher ----------------
extern "C" void kernel_launch(void* const* d_in, const int* in_sizes, int n_in,
                              void* d_out, int out_size) {
    const float* x    = (const float*)d_in[0];
    const int*   qw   = (const int*)  d_in[1];
    const float* qs   = (const float*)d_in[2];
    const float* bias = (const float*)d_in[3];
    const float* lA   = (const float*)d_in[4];
    const float* lB   = (const float*)d_in[5];
    float* out = (float*)d_out;

    cudaFuncSetAttribute(k_gemm, cudaFuncAttributeMaxDynamicSharedMemorySize, GEMM_SMEM);

    k_convert_x<<<4096, 256>>>(reinterpret_cast<const float4*>(x));
    k_fold_w<<<OUT_F / TO, 256>>>(qw, qs, lA, lB);
    k_gemm<<<dim3(OUT_F / BN, MTOT / BM), GEMM_THREADS, GEMM_SMEM>>>(bias, out);
}

// round 9
// speedup vs baseline: 1.5798x; 1.0097x over previous
#include <cuda_runtime.h>
#include <cuda_fp16.h>
#include <cstdint>
#include <cstddef>

#define IN_F   4096
#define OUT_F  4096
#define MTOT   8192   // 4 * 2048

// ---------------- scratch (static device globals: allocation-free) -----------
// Tile-major, pre-swizzled layouts (exactly what the GEMM wants in smem):
// g_Xh: [mtile128(64)][kchunk(64)] blocks of 16384B = 128 rows x 128B (swizzled)
// g_Wh: [ntile256(16)][kchunk(64)] blocks of 32768B = 256 rows x 128B (swizzled)
__device__ __half g_Xh[(size_t)MTOT * IN_F];   // 64 MiB
__device__ __half g_Wh[(size_t)OUT_F * IN_F];  // 32 MiB

// ---------------- PTX helpers ----------------
__device__ __forceinline__ uint32_t smem_u32(const void* p) {
    uint32_t r;
    asm("{ .reg .u64 t; cvta.to.shared.u64 t, %1; cvt.u32.u64 %0, t; }"
        : "=r"(r) : "l"(p));
    return r;
}
__device__ __forceinline__ void ldsm_x4(uint32_t* r, uint32_t addr) {
    asm volatile("ldmatrix.sync.aligned.m8n8.x4.shared.b16 {%0,%1,%2,%3}, [%4];"
                 : "=r"(r[0]), "=r"(r[1]), "=r"(r[2]), "=r"(r[3]) : "r"(addr));
}
__device__ __forceinline__ void mma16816(float* c, const uint32_t* a, const uint32_t* b) {
    asm volatile(
        "mma.sync.aligned.m16n8k16.row.col.f32.f16.f16.f32 "
        "{%0,%1,%2,%3}, {%4,%5,%6,%7}, {%8,%9}, {%0,%1,%2,%3};"
        : "+f"(c[0]), "+f"(c[1]), "+f"(c[2]), "+f"(c[3])
        : "r"(a[0]), "r"(a[1]), "r"(a[2]), "r"(a[3]), "r"(b[0]), "r"(b[1]));
}
__device__ __forceinline__ void bulk_g2s(uint32_t dst, const void* src, uint32_t bytes,
                                         uint32_t mbar) {
    asm volatile(
        "cp.async.bulk.shared::cta.global.mbarrier::complete_tx::bytes [%0], [%1], %2, [%3];"
        :: "r"(dst), "l"(src), "r"(bytes), "r"(mbar) : "memory");
}
#define MBARRIER_INIT(addr, cnt) \
    asm volatile("mbarrier.init.shared.b64 [%0], %1;" :: "r"((uint32_t)(addr)), "r"((uint32_t)(cnt)) : "memory")
#define MBARRIER_EXPECT_TX(addr, bytes) \
    asm volatile("mbarrier.arrive.expect_tx.shared.b64 _, [%0], %1;" :: "r"((uint32_t)(addr)), "r"((uint32_t)(bytes)) : "memory")
#define MBARRIER_WAIT_PARITY(mbar_smem_addr, phase_parity) do {                         \
    uint32_t _mbar = (uint32_t)(mbar_smem_addr);                                        \
    uint32_t _parity = (uint32_t)(phase_parity);                                        \
    uint32_t _done;                                                                     \
    asm volatile("{\n\t.reg .pred p;\n\t"                                               \
        "mbarrier.try_wait.parity.acquire.cta.shared::cta.b64 p, [%1], %2;\n\t"         \
        "selp.b32 %0, 1, 0, p;\n\t}"                                                    \
        : "=r"(_done) : "r"(_mbar), "r"(_parity) : "memory");                           \
    if (!_done) {                                                                       \
        asm volatile("{\n\t.reg .pred P1;\n\t"                                          \
            "WAIT_LOOP_%=:\n\t"                                                         \
            "mbarrier.try_wait.parity.acquire.cta.shared::cta.b64 P1, [%0], %1, 0x989680;\n\t" \
            "@P1 bra.uni WAIT_DONE_%=;\n\t"                                             \
            "bra.uni WAIT_LOOP_%=;\n\t"                                                 \
            "WAIT_DONE_%=:\n\t}"                                                        \
            :: "r"(_mbar), "r"(_parity) : "memory");                                    \
    }                                                                                   \
} while (0)

// ---------------- fused staging kernel -------------------------------------
// blocks [0, FOLD_BLOCKS): W_eff fold -> g_Wh (tile-major swizzled)
// blocks [FOLD_BLOCKS, ...): x fp32 -> fp16 -> g_Xh (tile-major swizzled)
#define TO 32
#define TI 512
#define FOLD_BLOCKS (OUT_F / TO)     // 128
#define CONV_BLOCKS 4096
#define STAGE_GRID (FOLD_BLOCKS + CONV_BLOCKS)

__global__ void k_stage(const float4* __restrict__ x,
                        const int* __restrict__ qw, const float* __restrict__ qs,
                        const float* __restrict__ A, const float* __restrict__ B) {
    const int tid = threadIdx.x;                  // 256
    if (blockIdx.x >= FOLD_BLOCKS) {
        // ---- convert x ----
        const int ngroups = MTOT * IN_F / 8;      // 16B groups
        int bid = blockIdx.x - FOLD_BLOCKS;
        int stride = CONV_BLOCKS * 256;
        for (int g = bid * 256 + tid; g < ngroups; g += stride) {
            float4 v0 = x[g * 2], v1 = x[g * 2 + 1];
            __half2 h0 = __floats2half2_rn(v0.x, v0.y);
            __half2 h1 = __floats2half2_rn(v0.z, v0.w);
            __half2 h2 = __floats2half2_rn(v1.x, v1.y);
            __half2 h3 = __floats2half2_rn(v1.z, v1.w);
            uint4 o;
            o.x = *reinterpret_cast<uint32_t*>(&h0);
            o.y = *reinterpret_cast<uint32_t*>(&h1);
            o.z = *reinterpret_cast<uint32_t*>(&h2);
            o.w = *reinterpret_cast<uint32_t*>(&h3);
            int m = g >> 9;                 // 512 groups per row
            int kg = g & 511;
            int kchunk = kg >> 3, chunk = kg & 7;
            int r = m & 127, mtile = m >> 7;
            size_t off = ((size_t)(mtile * 64 + kchunk) << 14)
                       + (uint32_t)(r * 128 + (((chunk ^ (r & 7)) & 7) << 4));
            *reinterpret_cast<uint4*>(reinterpret_cast<char*>(g_Xh) + off) = o;
        }
        return;
    }
    // ---- fold W ----
    __shared__ float As[16][TI + 4];
    __shared__ float Bs[TO][16];
    __shared__ float Ss[TO];
    const int o0 = blockIdx.x * TO;
    for (int t = tid; t < TO * 16; t += 256)
        Bs[t / 16][t % 16] = B[(size_t)(o0 + t / 16) * 16 + (t % 16)];
    if (tid < TO) Ss[tid] = qs[o0 + tid];
    const int ro = tid >> 3;    // row 0..31
    const int l8 = tid & 7;     // 0..7
    const int o = o0 + ro;
    const int ntile = o >> 8, rr = o & 255;
    for (int cb = 0; cb < IN_F; cb += TI) {
        __syncthreads();
        for (int t = tid; t < 16 * (TI / 4); t += 256) {
            int r = t / (TI / 4), j = t % (TI / 4);
            float4 v = reinterpret_cast<const float4*>(A + (size_t)r * IN_F + cb)[j];
            *reinterpret_cast<float4*>(&As[r][j * 4]) = v;
        }
        __syncthreads();
        const float s = Ss[ro];
        const float* brow = Bs[ro];
        #pragma unroll 4
        for (int j = 0; j < TI / 32; ++j) {
            int il = l8 * 4 + j * 32;
            int4 q4 = *reinterpret_cast<const int4*>(&qw[(size_t)o * IN_F + cb + il]);
            float a0 = q4.x * s, a1 = q4.y * s, a2 = q4.z * s, a3 = q4.w * s;
            #pragma unroll
            for (int r = 0; r < 16; ++r) {
                float b2 = 2.0f * brow[r];
                a0 = fmaf(b2, As[r][il + 0], a0);
                a1 = fmaf(b2, As[r][il + 1], a1);
                a2 = fmaf(b2, As[r][il + 2], a2);
                a3 = fmaf(b2, As[r][il + 3], a3);
            }
            __half2 h0 = __floats2half2_rn(a0, a1);
            __half2 h1 = __floats2half2_rn(a2, a3);
            uint2 w;
            w.x = *reinterpret_cast<uint32_t*>(&h0);
            w.y = *reinterpret_cast<uint32_t*>(&h1);
            int col = cb + il;
            int kchunk = col >> 6;
            int c6 = col & 63;
            int chunk = c6 >> 3, within = c6 & 7;   // within in {0,4}
            size_t off = ((size_t)(ntile * 64 + kchunk) << 15)
                       + (uint32_t)(rr * 128 + (((chunk ^ (rr & 7)) & 7) << 4) + within * 2);
            *reinterpret_cast<uint2*>(reinterpret_cast<char*>(g_Wh) + off) = w;
        }
    }
}

// ---------------- GEMM: bulk-DMA pipelined mma.sync, BM=256 x BN=128 --------
// 512 threads = 16 warps as 4(m) x 4(n); warp tile 64x32; 4 stages.
#define BM 256
#define BN 128
#define BK 64
#define NST 4
#define A_SZ (BM * 128)                   // 32768
#define B_SZ (BN * 128)                   // 16384
#define ST_SZ (A_SZ + B_SZ)               // 49152
#define SMEM_T0 1024
#define GEMM_SMEM (SMEM_T0 + NST * ST_SZ) // 197632
#define GEMM_THREADS 512
#define KCH (IN_F / BK)                   // 64

__global__ void __launch_bounds__(GEMM_THREADS, 1)
k_gemm(const float* __restrict__ bias, float* __restrict__ out) {
    extern __shared__ char smem[];
    uint32_t sb = smem_u32(smem);
    const int tid = threadIdx.x;
    const int wid = tid >> 5, lid = tid & 31;
    const int wm = wid & 3;          // 0..3  (m: 64-row slices)
    const int wn = wid >> 2;         // 0..3  (n: 32-col slices)
    const int mtile = blockIdx.y;    // 0..31 (256-row)
    const int ntile = blockIdx.x;    // 0..31 (128-col)
    // g_Xh blocks are 128-row; a BM=256 CTA spans two consecutive blocks.
    const char* gA = reinterpret_cast<const char*>(g_Xh) + ((size_t)(mtile * 2) * 64 << 14);
    // g_Wh blocks are 256-row x 32KB; rows are block-row-major so a 128-row
    // half is a contiguous 16KB at block_base + (ntile&1)*16384.
    const char* gB = reinterpret_cast<const char*>(g_Wh)
                   + ((size_t)(ntile >> 1) * 64 << 15) + (size_t)(ntile & 1) * 16384;

    float ac[4][4][4];
    #pragma unroll
    for (int i = 0; i < 4; ++i)
        #pragma unroll
        for (int j = 0; j < 4; ++j)
            #pragma unroll
            for (int k = 0; k < 4; ++k) ac[i][j][k] = 0.0f;

    if (tid == 0) {
        #pragma unroll
        for (int s = 0; s < NST; ++s) MBARRIER_INIT(sb + 8 * s, 1);
    }
    __syncthreads();

    if (tid == 0) {
        #pragma unroll
        for (int c = 0; c < NST; ++c) {
            uint32_t stg = sb + SMEM_T0 + c * ST_SZ;
            MBARRIER_EXPECT_TX(sb + 8 * c, ST_SZ);
            // A: two 16KB halves (rows 0-127 from block 2*mtile, 128-255 from 2*mtile+1)
            bulk_g2s(stg,             gA + ((size_t)c << 14),                A_SZ / 2, sb + 8 * c);
            bulk_g2s(stg + A_SZ / 2,  gA + (((size_t)64 + c) << 14),        A_SZ / 2, sb + 8 * c);
            bulk_g2s(stg + A_SZ,      gB + ((size_t)c << 15),               B_SZ,     sb + 8 * c);
        }
    }

    for (int c = 0; c < KCH; ++c) {
        int s = c & (NST - 1);
        MBARRIER_WAIT_PARITY(sb + 8 * s, (uint32_t)((c >> 2) & 1));

        uint32_t Ab = sb + SMEM_T0 + s * ST_SZ;
        uint32_t Bb = Ab + A_SZ;
        #pragma unroll
        for (int ks = 0; ks < BK / 16; ++ks) {       // 4
            uint32_t af[16], bf[8];
            #pragma unroll
            for (int i = 0; i < 4; ++i) {
                int row = wm * 64 + i * 16 + (lid & 15);
                int chunk = ks * 2 + (lid >> 4);
                uint32_t addr = Ab + (uint32_t)(row * 128) + (((chunk ^ (row & 7)) & 7) << 4);
                ldsm_x4(af + i * 4, addr);
            }
            #pragma unroll
            for (int j = 0; j < 2; ++j) {
                int row = wn * 32 + j * 16 + ((lid >> 4) << 3) + (lid & 7);
                int chunk = ks * 2 + ((lid >> 3) & 1);
                uint32_t addr = Bb + (uint32_t)(row * 128) + (((chunk ^ (row & 7)) & 7) << 4);
                ldsm_x4(bf + j * 4, addr);
            }
            #pragma unroll
            for (int i = 0; i < 4; ++i) {
                #pragma unroll
                for (int jj = 0; jj < 4; ++jj) {
                    mma16816(ac[i][jj], &af[i * 4], &bf[(jj >> 1) * 4 + (jj & 1) * 2]);
                }
            }
        }

        __syncthreads();   // all warps done reading stage s
        if (tid == 0 && c + NST < KCH) {
            int nc = c + NST;
            uint32_t stg = sb + SMEM_T0 + s * ST_SZ;
            MBARRIER_EXPECT_TX(sb + 8 * s, ST_SZ);
            bulk_g2s(stg,            gA + ((size_t)nc << 14),          A_SZ / 2, sb + 8 * s);
            bulk_g2s(stg + A_SZ / 2, gA + (((size_t)64 + nc) << 14),   A_SZ / 2, sb + 8 * s);
            bulk_g2s(stg + A_SZ,     gB + ((size_t)nc << 15),          B_SZ,     sb + 8 * s);
        }
    }

    // epilogue: write 64x32 warp tile with bias
    const int m0 = mtile * BM, n0 = ntile * BN;
    const int mbase = m0 + wm * 64 + (lid >> 2);
    const int nbase = n0 + wn * 32 + (lid & 3) * 2;
    #pragma unroll
    for (int jj = 0; jj < 4; ++jj) {
        int n = nbase + jj * 8;
        float b0 = bias[n], b1 = bias[n + 1];
        #pragma unroll
        for (int i = 0; i < 4; ++i) {
            int m = mbase + i * 16;
            float2 v0 = make_float2(ac[i][jj][0] + b0, ac[i][jj][1] + b1);
            float2 v1 = make_float2(ac[i][jj][2] + b0, ac[i][jj][3] + b1);
            *reinterpret_cast<float2*>(&out[(size_t)m * OUT_F + n]) = v0;
            *reinterpret_cast<float2*>(&out[(size_t)(m + 8) * OUT_F + n]) = v1;
        }
    }
}

// ---------------- launcher ----------------
extern "C" void kernel_launch(void* const* d_in, const int* in_sizes, int n_in,
                              void* d_out, int out_size) {
    const float* x    = (const float*)d_in[0];
    const int*   qw   = (const int*)  d_in[1];
    const float* qs   = (const float*)d_in[2];
    const float* bias = (const float*)d_in[3];
    const float* lA   = (const float*)d_in[4];
    const float* lB   = (const float*)d_in[5];
    float* out = (float*)d_out;

    cudaFuncSetAttribute(k_gemm, cudaFuncAttributeMaxDynamicSharedMemorySize, GEMM_SMEM);

    k_stage<<<STAGE_GRID, 256>>>(reinterpret_cast<const float4*>(x), qw, qs, lA, lB);
    k_gemm<<<dim3(OUT_F / BN, MTOT / BM), GEMM_THREADS, GEMM_SMEM>>>(bias, out);
}

// round 10
// speedup vs baseline: 1.7596x; 1.1138x over previous
#include <cuda_runtime.h>
#include <cuda_fp16.h>
#include <cstdint>
#include <cstddef>

#define IN_F   4096
#define OUT_F  4096
#define MTOT   8192   // 4 * 2048

// ---------------- scratch (static device globals: allocation-free) -----------
// Tile-major, pre-swizzled layouts (exactly what the GEMM wants in smem):
// g_Xh: [mtile128(64)][kchunk(64)] blocks of 16384B = 128 rows x 128B (swizzled)
// g_Wh: [ntile256(16)][kchunk(64)] blocks of 32768B = 256 rows x 128B (swizzled)
__device__ __half g_Xh[(size_t)MTOT * IN_F];   // 64 MiB
__device__ __half g_Wh[(size_t)OUT_F * IN_F];  // 32 MiB

// ---------------- PTX helpers ----------------
__device__ __forceinline__ uint32_t smem_u32(const void* p) {
    uint32_t r;
    asm("{ .reg .u64 t; cvta.to.shared.u64 t, %1; cvt.u32.u64 %0, t; }"
        : "=r"(r) : "l"(p));
    return r;
}
__device__ __forceinline__ void ldsm_x4(uint32_t* r, uint32_t addr) {
    asm volatile("ldmatrix.sync.aligned.m8n8.x4.shared.b16 {%0,%1,%2,%3}, [%4];"
                 : "=r"(r[0]), "=r"(r[1]), "=r"(r[2]), "=r"(r[3]) : "r"(addr));
}
__device__ __forceinline__ void mma16816(float* c, const uint32_t* a, const uint32_t* b) {
    asm volatile(
        "mma.sync.aligned.m16n8k16.row.col.f32.f16.f16.f32 "
        "{%0,%1,%2,%3}, {%4,%5,%6,%7}, {%8,%9}, {%0,%1,%2,%3};"
        : "+f"(c[0]), "+f"(c[1]), "+f"(c[2]), "+f"(c[3])
        : "r"(a[0]), "r"(a[1]), "r"(a[2]), "r"(a[3]), "r"(b[0]), "r"(b[1]));
}
__device__ __forceinline__ void bulk_g2s(uint32_t dst, const void* src, uint32_t bytes,
                                         uint32_t mbar) {
    asm volatile(
        "cp.async.bulk.shared::cta.global.mbarrier::complete_tx::bytes [%0], [%1], %2, [%3];"
        :: "r"(dst), "l"(src), "r"(bytes), "r"(mbar) : "memory");
}
#define MBARRIER_INIT(addr, cnt) \
    asm volatile("mbarrier.init.shared.b64 [%0], %1;" :: "r"((uint32_t)(addr)), "r"((uint32_t)(cnt)) : "memory")
#define MBARRIER_EXPECT_TX(addr, bytes) \
    asm volatile("mbarrier.arrive.expect_tx.shared.b64 _, [%0], %1;" :: "r"((uint32_t)(addr)), "r"((uint32_t)(bytes)) : "memory")
#define MBARRIER_WAIT_PARITY(mbar_smem_addr, phase_parity) do {                         \
    uint32_t _mbar = (uint32_t)(mbar_smem_addr);                                        \
    uint32_t _parity = (uint32_t)(phase_parity);                                        \
    uint32_t _done;                                                                     \
    asm volatile("{\n\t.reg .pred p;\n\t"                                               \
        "mbarrier.try_wait.parity.acquire.cta.shared::cta.b64 p, [%1], %2;\n\t"         \
        "selp.b32 %0, 1, 0, p;\n\t}"                                                    \
        : "=r"(_done) : "r"(_mbar), "r"(_parity) : "memory");                           \
    if (!_done) {                                                                       \
        asm volatile("{\n\t.reg .pred P1;\n\t"                                          \
            "WAIT_LOOP_%=:\n\t"                                                         \
            "mbarrier.try_wait.parity.acquire.cta.shared::cta.b64 P1, [%0], %1, 0x989680;\n\t" \
            "@P1 bra.uni WAIT_DONE_%=;\n\t"                                             \
            "bra.uni WAIT_LOOP_%=;\n\t"                                                 \
            "WAIT_DONE_%=:\n\t}"                                                        \
            :: "r"(_mbar), "r"(_parity) : "memory");                                    \
    }                                                                                   \
} while (0)

// ---------------- fused staging kernel -------------------------------------
#define TO 32
#define TI 512
#define FOLD_BLOCKS (OUT_F / TO)     // 128
#define CONV_BLOCKS 4096
#define STAGE_GRID (FOLD_BLOCKS + CONV_BLOCKS)

__global__ void k_stage(const float4* __restrict__ x,
                        const int* __restrict__ qw, const float* __restrict__ qs,
                        const float* __restrict__ A, const float* __restrict__ B) {
    const int tid = threadIdx.x;                  // 256
    if (blockIdx.x >= FOLD_BLOCKS) {
        // ---- convert x ----
        const int ngroups = MTOT * IN_F / 8;      // 16B groups
        int bid = blockIdx.x - FOLD_BLOCKS;
        int stride = CONV_BLOCKS * 256;
        for (int g = bid * 256 + tid; g < ngroups; g += stride) {
            float4 v0 = x[g * 2], v1 = x[g * 2 + 1];
            __half2 h0 = __floats2half2_rn(v0.x, v0.y);
            __half2 h1 = __floats2half2_rn(v0.z, v0.w);
            __half2 h2 = __floats2half2_rn(v1.x, v1.y);
            __half2 h3 = __floats2half2_rn(v1.z, v1.w);
            uint4 o;
            o.x = *reinterpret_cast<uint32_t*>(&h0);
            o.y = *reinterpret_cast<uint32_t*>(&h1);
            o.z = *reinterpret_cast<uint32_t*>(&h2);
            o.w = *reinterpret_cast<uint32_t*>(&h3);
            int m = g >> 9;                 // 512 groups per row
            int kg = g & 511;
            int kchunk = kg >> 3, chunk = kg & 7;
            int r = m & 127, mtile = m >> 7;
            size_t off = ((size_t)(mtile * 64 + kchunk) << 14)
                       + (uint32_t)(r * 128 + (((chunk ^ (r & 7)) & 7) << 4));
            *reinterpret_cast<uint4*>(reinterpret_cast<char*>(g_Xh) + off) = o;
        }
        return;
    }
    // ---- fold W ----
    __shared__ float As[16][TI + 4];
    __shared__ float Bs[TO][16];
    __shared__ float Ss[TO];
    const int o0 = blockIdx.x * TO;
    for (int t = tid; t < TO * 16; t += 256)
        Bs[t / 16][t % 16] = B[(size_t)(o0 + t / 16) * 16 + (t % 16)];
    if (tid < TO) Ss[tid] = qs[o0 + tid];
    const int ro = tid >> 3;    // row 0..31
    const int l8 = tid & 7;     // 0..7
    const int o = o0 + ro;
    const int ntile = o >> 8, rr = o & 255;
    for (int cb = 0; cb < IN_F; cb += TI) {
        __syncthreads();
        for (int t = tid; t < 16 * (TI / 4); t += 256) {
            int r = t / (TI / 4), j = t % (TI / 4);
            float4 v = reinterpret_cast<const float4*>(A + (size_t)r * IN_F + cb)[j];
            *reinterpret_cast<float4*>(&As[r][j * 4]) = v;
        }
        __syncthreads();
        const float s = Ss[ro];
        const float* brow = Bs[ro];
        #pragma unroll 4
        for (int j = 0; j < TI / 32; ++j) {
            int il = l8 * 4 + j * 32;
            int4 q4 = *reinterpret_cast<const int4*>(&qw[(size_t)o * IN_F + cb + il]);
            float a0 = q4.x * s, a1 = q4.y * s, a2 = q4.z * s, a3 = q4.w * s;
            #pragma unroll
            for (int r = 0; r < 16; ++r) {
                float b2 = 2.0f * brow[r];
                a0 = fmaf(b2, As[r][il + 0], a0);
                a1 = fmaf(b2, As[r][il + 1], a1);
                a2 = fmaf(b2, As[r][il + 2], a2);
                a3 = fmaf(b2, As[r][il + 3], a3);
            }
            __half2 h0 = __floats2half2_rn(a0, a1);
            __half2 h1 = __floats2half2_rn(a2, a3);
            uint2 w;
            w.x = *reinterpret_cast<uint32_t*>(&h0);
            w.y = *reinterpret_cast<uint32_t*>(&h1);
            int col = cb + il;
            int kchunk = col >> 6;
            int c6 = col & 63;
            int chunk = c6 >> 3, within = c6 & 7;   // within in {0,4}
            size_t off = ((size_t)(ntile * 64 + kchunk) << 15)
                       + (uint32_t)(rr * 128 + (((chunk ^ (rr & 7)) & 7) << 4) + within * 2);
            *reinterpret_cast<uint2*>(reinterpret_cast<char*>(g_Wh) + off) = w;
        }
    }
}

// ---------------- GEMM: bulk-DMA pipeline, BM=128 x BN=128, 2 CTAs/SM -------
// 256 threads = 8 warps as 2(m) x 4(n); warp tile 64x32; 3 stages (97 KB/CTA).
#define BM 128
#define BN 128
#define BK 64
#define NST 3
#define A_SZ (BM * 128)                   // 16384
#define B_SZ (BN * 128)                   // 16384
#define ST_SZ (A_SZ + B_SZ)               // 32768
#define SMEM_T0 1024
#define GEMM_SMEM (SMEM_T0 + NST * ST_SZ) // 99328
#define GEMM_THREADS 256
#define KCH (IN_F / BK)                   // 64

__global__ void __launch_bounds__(GEMM_THREADS, 2)
k_gemm(const float* __restrict__ bias, float* __restrict__ out) {
    extern __shared__ char smem[];
    uint32_t sb = smem_u32(smem);
    const int tid = threadIdx.x;
    const int wid = tid >> 5, lid = tid & 31;
    const int wm = wid & 1;          // 0..1  (m: 64-row halves)
    const int wn = wid >> 1;         // 0..3  (n: 32-col slices)
    const int mtile = blockIdx.y;    // 0..63 (128-row)
    const int ntile = blockIdx.x;    // 0..31 (128-col)
    const char* gA = reinterpret_cast<const char*>(g_Xh) + ((size_t)mtile * 64 << 14);
    // g_Wh blocks: 256 rows x 32KB per kchunk; 128-row half is contiguous 16KB.
    const char* gB = reinterpret_cast<const char*>(g_Wh)
                   + ((size_t)(ntile >> 1) * 64 << 15) + (size_t)(ntile & 1) * 16384;

    float ac[4][4][4];
    #pragma unroll
    for (int i = 0; i < 4; ++i)
        #pragma unroll
        for (int j = 0; j < 4; ++j)
            #pragma unroll
            for (int k = 0; k < 4; ++k) ac[i][j][k] = 0.0f;

    if (tid == 0) {
        #pragma unroll
        for (int s = 0; s < NST; ++s) MBARRIER_INIT(sb + 8 * s, 1);
    }
    __syncthreads();

    if (tid == 0) {
        #pragma unroll
        for (int c = 0; c < NST; ++c) {
            uint32_t stg = sb + SMEM_T0 + c * ST_SZ;
            MBARRIER_EXPECT_TX(sb + 8 * c, ST_SZ);
            bulk_g2s(stg,        gA + ((size_t)c << 14), A_SZ, sb + 8 * c);
            bulk_g2s(stg + A_SZ, gB + ((size_t)c << 15), B_SZ, sb + 8 * c);
        }
    }

    int s = 0, ph = 0;
    for (int c = 0; c < KCH; ++c) {
        MBARRIER_WAIT_PARITY(sb + 8 * s, (uint32_t)ph);

        uint32_t Ab = sb + SMEM_T0 + s * ST_SZ;
        uint32_t Bb = Ab + A_SZ;
        #pragma unroll
        for (int ks = 0; ks < BK / 16; ++ks) {       // 4
            uint32_t af[16], bf[8];
            #pragma unroll
            for (int i = 0; i < 4; ++i) {
                int row = wm * 64 + i * 16 + (lid & 15);
                int chunk = ks * 2 + (lid >> 4);
                uint32_t addr = Ab + (uint32_t)(row * 128) + (((chunk ^ (row & 7)) & 7) << 4);
                ldsm_x4(af + i * 4, addr);
            }
            #pragma unroll
            for (int j = 0; j < 2; ++j) {
                int row = wn * 32 + j * 16 + ((lid >> 4) << 3) + (lid & 7);
                int chunk = ks * 2 + ((lid >> 3) & 1);
                uint32_t addr = Bb + (uint32_t)(row * 128) + (((chunk ^ (row & 7)) & 7) << 4);
                ldsm_x4(bf + j * 4, addr);
            }
            #pragma unroll
            for (int i = 0; i < 4; ++i) {
                #pragma unroll
                for (int jj = 0; jj < 4; ++jj) {
                    mma16816(ac[i][jj], &af[i * 4], &bf[(jj >> 1) * 4 + (jj & 1) * 2]);
                }
            }
        }

        __syncthreads();   // all warps done reading stage s
        if (tid == 0 && c + NST < KCH) {
            int nc = c + NST;
            uint32_t stg = sb + SMEM_T0 + s * ST_SZ;
            MBARRIER_EXPECT_TX(sb + 8 * s, ST_SZ);
            bulk_g2s(stg,        gA + ((size_t)nc << 14), A_SZ, sb + 8 * s);
            bulk_g2s(stg + A_SZ, gB + ((size_t)nc << 15), B_SZ, sb + 8 * s);
        }
        ++s; if (s == NST) { s = 0; ph ^= 1; }
    }

    // epilogue: write 64x32 warp tile with bias
    const int m0 = mtile * BM, n0 = ntile * BN;
    const int mbase = m0 + wm * 64 + (lid >> 2);
    const int nbase = n0 + wn * 32 + (lid & 3) * 2;
    #pragma unroll
    for (int jj = 0; jj < 4; ++jj) {
        int n = nbase + jj * 8;
        float b0 = bias[n], b1 = bias[n + 1];
        #pragma unroll
        for (int i = 0; i < 4; ++i) {
            int m = mbase + i * 16;
            float2 v0 = make_float2(ac[i][jj][0] + b0, ac[i][jj][1] + b1);
            float2 v1 = make_float2(ac[i][jj][2] + b0, ac[i][jj][3] + b1);
            *reinterpret_cast<float2*>(&out[(size_t)m * OUT_F + n]) = v0;
            *reinterpret_cast<float2*>(&out[(size_t)(m + 8) * OUT_F + n]) = v1;
        }
    }
}

// ---------------- launcher ----------------
extern "C" void kernel_launch(void* const* d_in, const int* in_sizes, int n_in,
                              void* d_out, int out_size) {
    const float* x    = (const float*)d_in[0];
    const int*   qw   = (const int*)  d_in[1];
    const float* qs   = (const float*)d_in[2];
    const float* bias = (const float*)d_in[3];
    const float* lA   = (const float*)d_in[4];
    const float* lB   = (const float*)d_in[5];
    float* out = (float*)d_out;

    cudaFuncSetAttribute(k_gemm, cudaFuncAttributeMaxDynamicSharedMemorySize, GEMM_SMEM);

    k_stage<<<STAGE_GRID, 256>>>(reinterpret_cast<const float4*>(x), qw, qs, lA, lB);
    k_gemm<<<dim3(OUT_F / BN, MTOT / BM), GEMM_THREADS, GEMM_SMEM>>>(bias, out);
}

// round 11
// speedup vs baseline: 1.9100x; 1.0855x over previous
#include <cuda_runtime.h>
#include <cuda_fp16.h>
#include <cstdint>
#include <cstddef>

#define IN_F   4096
#define OUT_F  4096
#define MTOT   8192   // 4 * 2048

// ---------------- scratch (static device globals: allocation-free) -----------
// Tile-major, pre-swizzled layouts (exactly what the GEMM wants in smem):
// g_Xh: [mtile128(64)][kchunk(64)] blocks of 16384B = 128 rows x 128B (swizzled)
// g_Wh: [ntile256(16)][kchunk(64)] blocks of 32768B = 256 rows x 128B (swizzled)
__device__ __half g_Xh[(size_t)MTOT * IN_F];   // 64 MiB
__device__ __half g_Wh[(size_t)OUT_F * IN_F];  // 32 MiB

// ---------------- PTX helpers ----------------
__device__ __forceinline__ uint32_t smem_u32(const void* p) {
    uint32_t r;
    asm("{ .reg .u64 t; cvta.to.shared.u64 t, %1; cvt.u32.u64 %0, t; }"
        : "=r"(r) : "l"(p));
    return r;
}
__device__ __forceinline__ void ldsm_x4(uint32_t* r, uint32_t addr) {
    asm volatile("ldmatrix.sync.aligned.m8n8.x4.shared.b16 {%0,%1,%2,%3}, [%4];"
                 : "=r"(r[0]), "=r"(r[1]), "=r"(r[2]), "=r"(r[3]) : "r"(addr));
}
__device__ __forceinline__ void mma16816(float* c, const uint32_t* a, const uint32_t* b) {
    asm volatile(
        "mma.sync.aligned.m16n8k16.row.col.f32.f16.f16.f32 "
        "{%0,%1,%2,%3}, {%4,%5,%6,%7}, {%8,%9}, {%0,%1,%2,%3};"
        : "+f"(c[0]), "+f"(c[1]), "+f"(c[2]), "+f"(c[3])
        : "r"(a[0]), "r"(a[1]), "r"(a[2]), "r"(a[3]), "r"(b[0]), "r"(b[1]));
}
__device__ __forceinline__ void bulk_g2s(uint32_t dst, const void* src, uint32_t bytes,
                                         uint32_t mbar) {
    asm volatile(
        "cp.async.bulk.shared::cta.global.mbarrier::complete_tx::bytes [%0], [%1], %2, [%3];"
        :: "r"(dst), "l"(src), "r"(bytes), "r"(mbar) : "memory");
}
#define MBARRIER_INIT(addr, cnt) \
    asm volatile("mbarrier.init.shared.b64 [%0], %1;" :: "r"((uint32_t)(addr)), "r"((uint32_t)(cnt)) : "memory")
#define MBARRIER_EXPECT_TX(addr, bytes) \
    asm volatile("mbarrier.arrive.expect_tx.shared.b64 _, [%0], %1;" :: "r"((uint32_t)(addr)), "r"((uint32_t)(bytes)) : "memory")
#define MBARRIER_WAIT_PARITY(mbar_smem_addr, phase_parity) do {                         \
    uint32_t _mbar = (uint32_t)(mbar_smem_addr);                                        \
    uint32_t _parity = (uint32_t)(phase_parity);                                        \
    uint32_t _done;                                                                     \
    asm volatile("{\n\t.reg .pred p;\n\t"                                               \
        "mbarrier.try_wait.parity.acquire.cta.shared::cta.b64 p, [%1], %2;\n\t"         \
        "selp.b32 %0, 1, 0, p;\n\t}"                                                    \
        : "=r"(_done) : "r"(_mbar), "r"(_parity) : "memory");                           \
    if (!_done) {                                                                       \
        asm volatile("{\n\t.reg .pred P1;\n\t"                                          \
            "WAIT_LOOP_%=:\n\t"                                                         \
            "mbarrier.try_wait.parity.acquire.cta.shared::cta.b64 P1, [%0], %1, 0x989680;\n\t" \
            "@P1 bra.uni WAIT_DONE_%=;\n\t"                                             \
            "bra.uni WAIT_LOOP_%=;\n\t"                                                 \
            "WAIT_DONE_%=:\n\t}"                                                        \
            :: "r"(_mbar), "r"(_parity) : "memory");                                    \
    }                                                                                   \
} while (0)

// ---------------- fused staging kernel -------------------------------------
// blocks [0, FOLD_TOTAL): W_eff fold. 2D split: 128 row-strips x 8 col-strips.
// blocks [FOLD_TOTAL, ...): x fp32 -> fp16 tile-major swizzled convert.
#define TO 32
#define TI 512
#define FOLD_RS   (OUT_F / TO)       // 128 row strips
#define FOLD_CS   (IN_F / TI)        // 8 col strips
#define FOLD_TOTAL (FOLD_RS * FOLD_CS)   // 1024
#define CONV_BLOCKS 4096
#define STAGE_GRID (FOLD_TOTAL + CONV_BLOCKS)

__global__ void k_stage(const float4* __restrict__ x,
                        const int* __restrict__ qw, const float* __restrict__ qs,
                        const float* __restrict__ A, const float* __restrict__ B) {
    const int tid = threadIdx.x;                  // 256
    if (blockIdx.x >= FOLD_TOTAL) {
        // ---- convert x ----
        const int ngroups = MTOT * IN_F / 8;      // 16B groups
        int bid = blockIdx.x - FOLD_TOTAL;
        int stride = CONV_BLOCKS * 256;
        for (int g = bid * 256 + tid; g < ngroups; g += stride) {
            float4 v0 = x[g * 2], v1 = x[g * 2 + 1];
            __half2 h0 = __floats2half2_rn(v0.x, v0.y);
            __half2 h1 = __floats2half2_rn(v0.z, v0.w);
            __half2 h2 = __floats2half2_rn(v1.x, v1.y);
            __half2 h3 = __floats2half2_rn(v1.z, v1.w);
            uint4 o;
            o.x = *reinterpret_cast<uint32_t*>(&h0);
            o.y = *reinterpret_cast<uint32_t*>(&h1);
            o.z = *reinterpret_cast<uint32_t*>(&h2);
            o.w = *reinterpret_cast<uint32_t*>(&h3);
            int m = g >> 9;                 // 512 groups per row
            int kg = g & 511;
            int kchunk = kg >> 3, chunk = kg & 7;
            int r = m & 127, mtile = m >> 7;
            size_t off = ((size_t)(mtile * 64 + kchunk) << 14)
                       + (uint32_t)(r * 128 + (((chunk ^ (r & 7)) & 7) << 4));
            *reinterpret_cast<uint4*>(reinterpret_cast<char*>(g_Xh) + off) = o;
        }
        return;
    }
    // ---- fold W: one (32-row x 512-col) tile per block ----
    __shared__ float As[16][TI + 4];
    __shared__ float Bs[TO][16];
    __shared__ float Ss[TO];
    const int ob = blockIdx.x >> 3;              // row strip 0..127
    const int cb = (blockIdx.x & 7) * TI;        // col strip base
    const int o0 = ob * TO;
    for (int t = tid; t < TO * 16; t += 256)
        Bs[t / 16][t % 16] = B[(size_t)(o0 + t / 16) * 16 + (t % 16)];
    if (tid < TO) Ss[tid] = qs[o0 + tid];
    for (int t = tid; t < 16 * (TI / 4); t += 256) {
        int r = t / (TI / 4), j = t % (TI / 4);
        float4 v = reinterpret_cast<const float4*>(A + (size_t)r * IN_F + cb)[j];
        *reinterpret_cast<float4*>(&As[r][j * 4]) = v;
    }
    __syncthreads();
    const int ro = tid >> 3;    // row 0..31
    const int l8 = tid & 7;     // 0..7
    const int o = o0 + ro;
    const int ntile = o >> 8, rr = o & 255;
    const float s = Ss[ro];
    const float* brow = Bs[ro];
    #pragma unroll 4
    for (int j = 0; j < TI / 32; ++j) {
        int il = l8 * 4 + j * 32;
        int4 q4 = *reinterpret_cast<const int4*>(&qw[(size_t)o * IN_F + cb + il]);
        float a0 = q4.x * s, a1 = q4.y * s, a2 = q4.z * s, a3 = q4.w * s;
        #pragma unroll
        for (int r = 0; r < 16; ++r) {
            float b2 = 2.0f * brow[r];
            a0 = fmaf(b2, As[r][il + 0], a0);
            a1 = fmaf(b2, As[r][il + 1], a1);
            a2 = fmaf(b2, As[r][il + 2], a2);
            a3 = fmaf(b2, As[r][il + 3], a3);
        }
        __half2 h0 = __floats2half2_rn(a0, a1);
        __half2 h1 = __floats2half2_rn(a2, a3);
        uint2 w;
        w.x = *reinterpret_cast<uint32_t*>(&h0);
        w.y = *reinterpret_cast<uint32_t*>(&h1);
        int col = cb + il;
        int kchunk = col >> 6;
        int c6 = col & 63;
        int chunk = c6 >> 3, within = c6 & 7;   // within in {0,4}
        size_t off = ((size_t)(ntile * 64 + kchunk) << 15)
                   + (uint32_t)(rr * 128 + (((chunk ^ (rr & 7)) & 7) << 4) + within * 2);
        *reinterpret_cast<uint2*>(reinterpret_cast<char*>(g_Wh) + off) = w;
    }
}

// ---------------- GEMM: bulk-DMA pipeline, BM=128 x BN=128, 2 CTAs/SM -------
// 256 threads = 8 warps as 2(m) x 4(n); warp tile 64x32; 3 stages (97 KB/CTA).
#define BM 128
#define BN 128
#define BK 64
#define NST 3
#define A_SZ (BM * 128)                   // 16384
#define B_SZ (BN * 128)                   // 16384
#define ST_SZ (A_SZ + B_SZ)               // 32768
#define SMEM_T0 1024
#define GEMM_SMEM (SMEM_T0 + NST * ST_SZ) // 99328
#define GEMM_THREADS 256
#define KCH (IN_F / BK)                   // 64

__global__ void __launch_bounds__(GEMM_THREADS, 2)
k_gemm(const float* __restrict__ bias, float* __restrict__ out) {
    extern __shared__ char smem[];
    uint32_t sb = smem_u32(smem);
    const int tid = threadIdx.x;
    const int wid = tid >> 5, lid = tid & 31;
    const int wm = wid & 1;          // 0..1  (m: 64-row halves)
    const int wn = wid >> 1;         // 0..3  (n: 32-col slices)
    const int mtile = blockIdx.y;    // 0..63 (128-row)
    const int ntile = blockIdx.x;    // 0..31 (128-col)
    const char* gA = reinterpret_cast<const char*>(g_Xh) + ((size_t)mtile * 64 << 14);
    const char* gB = reinterpret_cast<const char*>(g_Wh)
                   + ((size_t)(ntile >> 1) * 64 << 15) + (size_t)(ntile & 1) * 16384;

    float ac[4][4][4];
    #pragma unroll
    for (int i = 0; i < 4; ++i)
        #pragma unroll
        for (int j = 0; j < 4; ++j)
            #pragma unroll
            for (int k = 0; k < 4; ++k) ac[i][j][k] = 0.0f;

    if (tid == 0) {
        #pragma unroll
        for (int s = 0; s < NST; ++s) MBARRIER_INIT(sb + 8 * s, 1);
    }
    __syncthreads();

    if (tid == 0) {
        #pragma unroll
        for (int c = 0; c < NST; ++c) {
            uint32_t stg = sb + SMEM_T0 + c * ST_SZ;
            MBARRIER_EXPECT_TX(sb + 8 * c, ST_SZ);
            bulk_g2s(stg,        gA + ((size_t)c << 14), A_SZ, sb + 8 * c);
            bulk_g2s(stg + A_SZ, gB + ((size_t)c << 15), B_SZ, sb + 8 * c);
        }
    }

    int s = 0, ph = 0;
    for (int c = 0; c < KCH; ++c) {
        MBARRIER_WAIT_PARITY(sb + 8 * s, (uint32_t)ph);

        uint32_t Ab = sb + SMEM_T0 + s * ST_SZ;
        uint32_t Bb = Ab + A_SZ;
        #pragma unroll
        for (int ks = 0; ks < BK / 16; ++ks) {       // 4
            uint32_t af[16], bf[8];
            #pragma unroll
            for (int i = 0; i < 4; ++i) {
                int row = wm * 64 + i * 16 + (lid & 15);
                int chunk = ks * 2 + (lid >> 4);
                uint32_t addr = Ab + (uint32_t)(row * 128) + (((chunk ^ (row & 7)) & 7) << 4);
                ldsm_x4(af + i * 4, addr);
            }
            #pragma unroll
            for (int j = 0; j < 2; ++j) {
                int row = wn * 32 + j * 16 + ((lid >> 4) << 3) + (lid & 7);
                int chunk = ks * 2 + ((lid >> 3) & 1);
                uint32_t addr = Bb + (uint32_t)(row * 128) + (((chunk ^ (row & 7)) & 7) << 4);
                ldsm_x4(bf + j * 4, addr);
            }
            #pragma unroll
            for (int i = 0; i < 4; ++i) {
                #pragma unroll
                for (int jj = 0; jj < 4; ++jj) {
                    mma16816(ac[i][jj], &af[i * 4], &bf[(jj >> 1) * 4 + (jj & 1) * 2]);
                }
            }
        }

        __syncthreads();   // all warps done reading stage s
        if (tid == 0 && c + NST < KCH) {
            int nc = c + NST;
            uint32_t stg = sb + SMEM_T0 + s * ST_SZ;
            MBARRIER_EXPECT_TX(sb + 8 * s, ST_SZ);
            bulk_g2s(stg,        gA + ((size_t)nc << 14), A_SZ, sb + 8 * s);
            bulk_g2s(stg + A_SZ, gB + ((size_t)nc << 15), B_SZ, sb + 8 * s);
        }
        ++s; if (s == NST) { s = 0; ph ^= 1; }
    }

    // epilogue: write 64x32 warp tile with bias
    const int m0 = mtile * BM, n0 = ntile * BN;
    const int mbase = m0 + wm * 64 + (lid >> 2);
    const int nbase = n0 + wn * 32 + (lid & 3) * 2;
    #pragma unroll
    for (int jj = 0; jj < 4; ++jj) {
        int n = nbase + jj * 8;
        float b0 = bias[n], b1 = bias[n + 1];
        #pragma unroll
        for (int i = 0; i < 4; ++i) {
            int m = mbase + i * 16;
            float2 v0 = make_float2(ac[i][jj][0] + b0, ac[i][jj][1] + b1);
            float2 v1 = make_float2(ac[i][jj][2] + b0, ac[i][jj][3] + b1);
            *reinterpret_cast<float2*>(&out[(size_t)m * OUT_F + n]) = v0;
            *reinterpret_cast<float2*>(&out[(size_t)(m + 8) * OUT_F + n]) = v1;
        }
    }
}

// ---------------- launcher ----------------
extern "C" void kernel_launch(void* const* d_in, const int* in_sizes, int n_in,
                              void* d_out, int out_size) {
    const float* x    = (const float*)d_in[0];
    const int*   qw   = (const int*)  d_in[1];
    const float* qs   = (const float*)d_in[2];
    const float* bias = (const float*)d_in[3];
    const float* lA   = (const float*)d_in[4];
    const float* lB   = (const float*)d_in[5];
    float* out = (float*)d_out;

    cudaFuncSetAttribute(k_gemm, cudaFuncAttributeMaxDynamicSharedMemorySize, GEMM_SMEM);

    k_stage<<<STAGE_GRID, 256>>>(reinterpret_cast<const float4*>(x), qw, qs, lA, lB);
    k_gemm<<<dim3(OUT_F / BN, MTOT / BM), GEMM_THREADS, GEMM_SMEM>>>(bias, out);
}

// round 12
// speedup vs baseline: 1.9572x; 1.0247x over previous
#include <cuda_runtime.h>
#include <cuda_fp16.h>
#include <cstdint>
#include <cstddef>

#define IN_F   4096
#define OUT_F  4096
#define MTOT   8192   // 4 * 2048

// ---------------- scratch (static device globals: allocation-free) -----------
// Tile-major, pre-swizzled layouts (exactly what the GEMM wants in smem):
// g_Xh: [mtile128(64)][kchunk(64)] blocks of 16384B = 128 rows x 128B (swizzled)
// g_Wh: [ntile256(16)][kchunk(64)] blocks of 32768B = 256 rows x 128B (swizzled)
__device__ __half g_Xh[(size_t)MTOT * IN_F];   // 64 MiB
__device__ __half g_Wh[(size_t)OUT_F * IN_F];  // 32 MiB

// ---------------- PTX helpers ----------------
__device__ __forceinline__ uint32_t smem_u32(const void* p) {
    uint32_t r;
    asm("{ .reg .u64 t; cvta.to.shared.u64 t, %1; cvt.u32.u64 %0, t; }"
        : "=r"(r) : "l"(p));
    return r;
}
__device__ __forceinline__ void ldsm_x4(uint32_t* r, uint32_t addr) {
    asm volatile("ldmatrix.sync.aligned.m8n8.x4.shared.b16 {%0,%1,%2,%3}, [%4];"
                 : "=r"(r[0]), "=r"(r[1]), "=r"(r[2]), "=r"(r[3]) : "r"(addr));
}
__device__ __forceinline__ void mma16816(float* c, const uint32_t* a, const uint32_t* b) {
    asm volatile(
        "mma.sync.aligned.m16n8k16.row.col.f32.f16.f16.f32 "
        "{%0,%1,%2,%3}, {%4,%5,%6,%7}, {%8,%9}, {%0,%1,%2,%3};"
        : "+f"(c[0]), "+f"(c[1]), "+f"(c[2]), "+f"(c[3])
        : "r"(a[0]), "r"(a[1]), "r"(a[2]), "r"(a[3]), "r"(b[0]), "r"(b[1]));
}
__device__ __forceinline__ void bulk_g2s(uint32_t dst, const void* src, uint32_t bytes,
                                         uint32_t mbar) {
    asm volatile(
        "cp.async.bulk.shared::cta.global.mbarrier::complete_tx::bytes [%0], [%1], %2, [%3];"
        :: "r"(dst), "l"(src), "r"(bytes), "r"(mbar) : "memory");
}
#define MBARRIER_INIT(addr, cnt) \
    asm volatile("mbarrier.init.shared.b64 [%0], %1;" :: "r"((uint32_t)(addr)), "r"((uint32_t)(cnt)) : "memory")
#define MBARRIER_EXPECT_TX(addr, bytes) \
    asm volatile("mbarrier.arrive.expect_tx.shared.b64 _, [%0], %1;" :: "r"((uint32_t)(addr)), "r"((uint32_t)(bytes)) : "memory")
#define MBARRIER_ARRIVE(addr) \
    asm volatile("mbarrier.arrive.release.cta.shared::cta.b64 _, [%0];" :: "r"((uint32_t)(addr)) : "memory")
#define MBARRIER_WAIT_PARITY(mbar_smem_addr, phase_parity) do {                         \
    uint32_t _mbar = (uint32_t)(mbar_smem_addr);                                        \
    uint32_t _parity = (uint32_t)(phase_parity);                                        \
    uint32_t _done;                                                                     \
    asm volatile("{\n\t.reg .pred p;\n\t"                                               \
        "mbarrier.try_wait.parity.acquire.cta.shared::cta.b64 p, [%1], %2;\n\t"         \
        "selp.b32 %0, 1, 0, p;\n\t}"                                                    \
        : "=r"(_done) : "r"(_mbar), "r"(_parity) : "memory");                           \
    if (!_done) {                                                                       \
        asm volatile("{\n\t.reg .pred P1;\n\t"                                          \
            "WAIT_LOOP_%=:\n\t"                                                         \
            "mbarrier.try_wait.parity.acquire.cta.shared::cta.b64 P1, [%0], %1, 0x989680;\n\t" \
            "@P1 bra.uni WAIT_DONE_%=;\n\t"                                             \
            "bra.uni WAIT_LOOP_%=;\n\t"                                                 \
            "WAIT_DONE_%=:\n\t}"                                                        \
            :: "r"(_mbar), "r"(_parity) : "memory");                                    \
    }                                                                                   \
} while (0)

// ---------------- fused staging kernel -------------------------------------
// blocks [0, FOLD_TOTAL): W_eff fold. 2D split: 128 row-strips x 8 col-strips.
// blocks [FOLD_TOTAL, ...): x fp32 -> fp16 tile-major swizzled convert.
#define TO 32
#define TI 512
#define FOLD_RS   (OUT_F / TO)       // 128 row strips
#define FOLD_CS   (IN_F / TI)        // 8 col strips
#define FOLD_TOTAL (FOLD_RS * FOLD_CS)   // 1024
#define CONV_BLOCKS 4096
#define STAGE_GRID (FOLD_TOTAL + CONV_BLOCKS)

__global__ void k_stage(const float4* __restrict__ x,
                        const int* __restrict__ qw, const float* __restrict__ qs,
                        const float* __restrict__ A, const float* __restrict__ B) {
    const int tid = threadIdx.x;                  // 256
    if (blockIdx.x >= FOLD_TOTAL) {
        // ---- convert x ----
        const int ngroups = MTOT * IN_F / 8;      // 16B groups
        int bid = blockIdx.x - FOLD_TOTAL;
        int stride = CONV_BLOCKS * 256;
        for (int g = bid * 256 + tid; g < ngroups; g += stride) {
            float4 v0 = x[g * 2], v1 = x[g * 2 + 1];
            __half2 h0 = __floats2half2_rn(v0.x, v0.y);
            __half2 h1 = __floats2half2_rn(v0.z, v0.w);
            __half2 h2 = __floats2half2_rn(v1.x, v1.y);
            __half2 h3 = __floats2half2_rn(v1.z, v1.w);
            uint4 o;
            o.x = *reinterpret_cast<uint32_t*>(&h0);
            o.y = *reinterpret_cast<uint32_t*>(&h1);
            o.z = *reinterpret_cast<uint32_t*>(&h2);
            o.w = *reinterpret_cast<uint32_t*>(&h3);
            int m = g >> 9;                 // 512 groups per row
            int kg = g & 511;
            int kchunk = kg >> 3, chunk = kg & 7;
            int r = m & 127, mtile = m >> 7;
            size_t off = ((size_t)(mtile * 64 + kchunk) << 14)
                       + (uint32_t)(r * 128 + (((chunk ^ (r & 7)) & 7) << 4));
            *reinterpret_cast<uint4*>(reinterpret_cast<char*>(g_Xh) + off) = o;
        }
        return;
    }
    // ---- fold W: one (32-row x 512-col) tile per block ----
    __shared__ float As[16][TI + 4];
    __shared__ float Bs[TO][16];
    __shared__ float Ss[TO];
    const int ob = blockIdx.x >> 3;              // row strip 0..127
    const int cb = (blockIdx.x & 7) * TI;        // col strip base
    const int o0 = ob * TO;
    for (int t = tid; t < TO * 16; t += 256)
        Bs[t / 16][t % 16] = B[(size_t)(o0 + t / 16) * 16 + (t % 16)];
    if (tid < TO) Ss[tid] = qs[o0 + tid];
    for (int t = tid; t < 16 * (TI / 4); t += 256) {
        int r = t / (TI / 4), j = t % (TI / 4);
        float4 v = reinterpret_cast<const float4*>(A + (size_t)r * IN_F + cb)[j];
        *reinterpret_cast<float4*>(&As[r][j * 4]) = v;
    }
    __syncthreads();
    const int ro = tid >> 3;    // row 0..31
    const int l8 = tid & 7;     // 0..7
    const int o = o0 + ro;
    const int ntile = o >> 8, rr = o & 255;
    const float s = Ss[ro];
    const float* brow = Bs[ro];
    #pragma unroll 4
    for (int j = 0; j < TI / 32; ++j) {
        int il = l8 * 4 + j * 32;
        int4 q4 = *reinterpret_cast<const int4*>(&qw[(size_t)o * IN_F + cb + il]);
        float a0 = q4.x * s, a1 = q4.y * s, a2 = q4.z * s, a3 = q4.w * s;
        #pragma unroll
        for (int r = 0; r < 16; ++r) {
            float b2 = 2.0f * brow[r];
            a0 = fmaf(b2, As[r][il + 0], a0);
            a1 = fmaf(b2, As[r][il + 1], a1);
            a2 = fmaf(b2, As[r][il + 2], a2);
            a3 = fmaf(b2, As[r][il + 3], a3);
        }
        __half2 h0 = __floats2half2_rn(a0, a1);
        __half2 h1 = __floats2half2_rn(a2, a3);
        uint2 w;
        w.x = *reinterpret_cast<uint32_t*>(&h0);
        w.y = *reinterpret_cast<uint32_t*>(&h1);
        int col = cb + il;
        int kchunk = col >> 6;
        int c6 = col & 63;
        int chunk = c6 >> 3, within = c6 & 7;   // within in {0,4}
        size_t off = ((size_t)(ntile * 64 + kchunk) << 15)
                   + (uint32_t)(rr * 128 + (((chunk ^ (rr & 7)) & 7) << 4) + within * 2);
        *reinterpret_cast<uint2*>(reinterpret_cast<char*>(g_Wh) + off) = w;
    }
}

// ---------------- GEMM: bulk-DMA pipeline, BM=128 x BN=128, 2 CTAs/SM -------
// 256 threads = 8 warps as 2(m) x 4(n); warp tile 64x32; 3 stages (97 KB/CTA).
// Full/empty mbarrier producer-consumer: no block-wide __syncthreads in loop.
#define BM 128
#define BN 128
#define BK 64
#define NST 3
#define A_SZ (BM * 128)                   // 16384
#define B_SZ (BN * 128)                   // 16384
#define ST_SZ (A_SZ + B_SZ)               // 32768
#define SMEM_T0 1024
#define GEMM_SMEM (SMEM_T0 + NST * ST_SZ) // 99328
#define GEMM_THREADS 256
#define KCH (IN_F / BK)                   // 64
#define FULL_BAR(sb, s)  ((sb) + 8 * (s))          // [0, 24)
#define EMPTY_BAR(sb, s) ((sb) + 24 + 8 * (s))     // [24, 48)

__global__ void __launch_bounds__(GEMM_THREADS, 2)
k_gemm(const float* __restrict__ bias, float* __restrict__ out) {
    extern __shared__ char smem[];
    uint32_t sb = smem_u32(smem);
    const int tid = threadIdx.x;
    const int wid = tid >> 5, lid = tid & 31;
    const int wm = wid & 1;          // 0..1  (m: 64-row halves)
    const int wn = wid >> 1;         // 0..3  (n: 32-col slices)
    const int mtile = blockIdx.y;    // 0..63 (128-row)
    const int ntile = blockIdx.x;    // 0..31 (128-col)
    const char* gA = reinterpret_cast<const char*>(g_Xh) + ((size_t)mtile * 64 << 14);
    const char* gB = reinterpret_cast<const char*>(g_Wh)
                   + ((size_t)(ntile >> 1) * 64 << 15) + (size_t)(ntile & 1) * 16384;

    float ac[4][4][4];
    #pragma unroll
    for (int i = 0; i < 4; ++i)
        #pragma unroll
        for (int j = 0; j < 4; ++j)
            #pragma unroll
            for (int k = 0; k < 4; ++k) ac[i][j][k] = 0.0f;

    if (tid == 0) {
        #pragma unroll
        for (int s = 0; s < NST; ++s) {
            MBARRIER_INIT(FULL_BAR(sb, s), 1);
            MBARRIER_INIT(EMPTY_BAR(sb, s), 8);   // one arrive per warp
        }
    }
    __syncthreads();

    if (tid == 0) {
        #pragma unroll
        for (int c = 0; c < NST; ++c) {
            uint32_t stg = sb + SMEM_T0 + c * ST_SZ;
            MBARRIER_EXPECT_TX(FULL_BAR(sb, c), ST_SZ);
            bulk_g2s(stg,        gA + ((size_t)c << 14), A_SZ, FULL_BAR(sb, c));
            bulk_g2s(stg + A_SZ, gB + ((size_t)c << 15), B_SZ, FULL_BAR(sb, c));
        }
    }

    int s = 0, q = 0;    // stage = c % NST, q = c / NST; parity = q & 1
    for (int c = 0; c < KCH; ++c) {
        MBARRIER_WAIT_PARITY(FULL_BAR(sb, s), (uint32_t)(q & 1));

        uint32_t Ab = sb + SMEM_T0 + s * ST_SZ;
        uint32_t Bb = Ab + A_SZ;
        #pragma unroll
        for (int ks = 0; ks < BK / 16; ++ks) {       // 4
            uint32_t af[16], bf[8];
            #pragma unroll
            for (int i = 0; i < 4; ++i) {
                int row = wm * 64 + i * 16 + (lid & 15);
                int chunk = ks * 2 + (lid >> 4);
                uint32_t addr = Ab + (uint32_t)(row * 128) + (((chunk ^ (row & 7)) & 7) << 4);
                ldsm_x4(af + i * 4, addr);
            }
            #pragma unroll
            for (int j = 0; j < 2; ++j) {
                int row = wn * 32 + j * 16 + ((lid >> 4) << 3) + (lid & 7);
                int chunk = ks * 2 + ((lid >> 3) & 1);
                uint32_t addr = Bb + (uint32_t)(row * 128) + (((chunk ^ (row & 7)) & 7) << 4);
                ldsm_x4(bf + j * 4, addr);
            }
            #pragma unroll
            for (int i = 0; i < 4; ++i) {
                #pragma unroll
                for (int jj = 0; jj < 4; ++jj) {
                    mma16816(ac[i][jj], &af[i * 4], &bf[(jj >> 1) * 4 + (jj & 1) * 2]);
                }
            }
        }

        // this warp is done reading stage s for consumption q
        if (lid == 0) MBARRIER_ARRIVE(EMPTY_BAR(sb, s));

        // producer: refill stage s with chunk c+NST once all 8 warps arrived
        if (tid == 0 && c + NST < KCH) {
            MBARRIER_WAIT_PARITY(EMPTY_BAR(sb, s), (uint32_t)(q & 1));
            int nc = c + NST;
            uint32_t stg = sb + SMEM_T0 + s * ST_SZ;
            MBARRIER_EXPECT_TX(FULL_BAR(sb, s), ST_SZ);
            bulk_g2s(stg,        gA + ((size_t)nc << 14), A_SZ, FULL_BAR(sb, s));
            bulk_g2s(stg + A_SZ, gB + ((size_t)nc << 15), B_SZ, FULL_BAR(sb, s));
        }
        ++s; if (s == NST) { s = 0; ++q; }
    }

    // epilogue: write 64x32 warp tile with bias (per-warp, no sync needed)
    const int m0 = mtile * BM, n0 = ntile * BN;
    const int mbase = m0 + wm * 64 + (lid >> 2);
    const int nbase = n0 + wn * 32 + (lid & 3) * 2;
    #pragma unroll
    for (int jj = 0; jj < 4; ++jj) {
        int n = nbase + jj * 8;
        float b0 = bias[n], b1 = bias[n + 1];
        #pragma unroll
        for (int i = 0; i < 4; ++i) {
            int m = mbase + i * 16;
            float2 v0 = make_float2(ac[i][jj][0] + b0, ac[i][jj][1] + b1);
            float2 v1 = make_float2(ac[i][jj][2] + b0, ac[i][jj][3] + b1);
            *reinterpret_cast<float2*>(&out[(size_t)m * OUT_F + n]) = v0;
            *reinterpret_cast<float2*>(&out[(size_t)(m + 8) * OUT_F + n]) = v1;
        }
    }
}

// ---------------- launcher ----------------
extern "C" void kernel_launch(void* const* d_in, const int* in_sizes, int n_in,
                              void* d_out, int out_size) {
    const float* x    = (const float*)d_in[0];
    const int*   qw   = (const int*)  d_in[1];
    const float* qs   = (const float*)d_in[2];
    const float* bias = (const float*)d_in[3];
    const float* lA   = (const float*)d_in[4];
    const float* lB   = (const float*)d_in[5];
    float* out = (float*)d_out;

    cudaFuncSetAttribute(k_gemm, cudaFuncAttributeMaxDynamicSharedMemorySize, GEMM_SMEM);

    k_stage<<<STAGE_GRID, 256>>>(reinterpret_cast<const float4*>(x), qw, qs, lA, lB);
    k_gemm<<<dim3(OUT_F / BN, MTOT / BM), GEMM_THREADS, GEMM_SMEM>>>(bias, out);
}